// round 6
// baseline (speedup 1.0000x reference)
#include <cuda_runtime.h>
#include <math.h>

// dims
#define Bq 16
#define Tt 120
#define Nj 24
#define Dd 256
#define Hh 8
#define DPp 32
#define TOT (Bq*Tt*Nj*Dd)   // 11,796,480
#define LDJ (Nj*Dd)         // 6144

// scratch buffers (static device memory is allowed; cudaMalloc is not)
__device__ float g_qt[TOT];
__device__ float g_kt[TOT];
__device__ float g_vt[TOT];
__device__ float g_qs[TOT];
__device__ float g_ks[TOT];
__device__ float g_vs[TOT];
__device__ float g_ta[TOT];
__device__ float g_sa[TOT];
__device__ float g_to[TOT];
__device__ float g_y[TOT];
__device__ float g_h[TOT];

// ---------------------------------------------------------------------------
// Tiled SGEMM: C = A @ W + bias with fused epilogues.
// K = 256, Nout = 256 fixed. 128x128 block tile, 8x8 micro-tile, K-chunk 8,
// double-buffered smem, float4 LDS. blockIdx.z = joint.
// epi: 0 = bias, 1 = bias+relu, 2 = bias + R1, 3 = bias + R1 + R2
// ---------------------------------------------------------------------------
__global__ void __launch_bounds__(256, 2) gemm256(
    const float* __restrict__ A, int ldA, int aJ,
    const float* __restrict__ W, int wJ,
    const float* __restrict__ bias, int bJ,
    float* __restrict__ C, int ldC, int cJ,
    const float* __restrict__ R1, const float* __restrict__ R2,
    int epi)
{
    __shared__ float As[2][8][128];   // [buf][k][m]
    __shared__ float Bs[2][8][128];   // [buf][k][n]

    const int j = blockIdx.z;
    const float* Ab = A + (size_t)j * aJ;
    const float* Wb = W + (size_t)j * wJ;
    const float* bb = bias + (size_t)j * bJ;
    float* Cb = C + (size_t)j * cJ;
    const float* R1b = R1 ? (R1 + (size_t)j * cJ) : nullptr;
    const float* R2b = R2 ? (R2 + (size_t)j * cJ) : nullptr;

    const int row0 = blockIdx.x * 128;
    const int n0   = blockIdx.y * 128;
    const int tid = threadIdx.x;
    const int tx = tid & 15;          // 0..15 -> col group
    const int ty = tid >> 4;          // 0..15 -> row group

    // A load map: 128 rows x 8 k = 256 float4 along K
    const int ar = tid >> 1;          // row in tile
    const int ak = (tid & 1) * 4;     // k offset (0 or 4)
    // B load map: 8 k x 128 n = 256 float4 along N
    const int bk = tid >> 5;          // 0..7
    const int bn = (tid & 31) * 4;    // 0..124

    const float* Aptr = Ab + (size_t)(row0 + ar) * ldA + ak;
    const float* Wptr = Wb + (size_t)bk * 256 + n0 + bn;

    float c[8][8];
#pragma unroll
    for (int i = 0; i < 8; i++)
#pragma unroll
        for (int q = 0; q < 8; q++) c[i][q] = 0.f;

    // stage chunk 0
    {
        float4 av = *(const float4*)Aptr;
        float4 bv = *(const float4*)Wptr;
        As[0][ak + 0][ar] = av.x;
        As[0][ak + 1][ar] = av.y;
        As[0][ak + 2][ar] = av.z;
        As[0][ak + 3][ar] = av.w;
        *(float4*)&Bs[0][bk][bn] = bv;
    }
    __syncthreads();

    int buf = 0;
    for (int k0 = 0; k0 < 256; k0 += 8) {
        float4 av, bv;
        const bool more = (k0 + 8) < 256;
        if (more) {
            av = *(const float4*)(Aptr + k0 + 8);
            bv = *(const float4*)(Wptr + (size_t)(k0 + 8) * 256);
        }

#pragma unroll
        for (int kk = 0; kk < 8; kk++) {
            const float4 a0 = *(const float4*)&As[buf][kk][ty * 4];
            const float4 a1 = *(const float4*)&As[buf][kk][64 + ty * 4];
            const float4 b0 = *(const float4*)&Bs[buf][kk][tx * 4];
            const float4 b1 = *(const float4*)&Bs[buf][kk][64 + tx * 4];
            const float a[8] = {a0.x, a0.y, a0.z, a0.w, a1.x, a1.y, a1.z, a1.w};
            const float b[8] = {b0.x, b0.y, b0.z, b0.w, b1.x, b1.y, b1.z, b1.w};
#pragma unroll
            for (int i = 0; i < 8; i++)
#pragma unroll
                for (int q = 0; q < 8; q++)
                    c[i][q] += a[i] * b[q];
        }

        if (more) {
            buf ^= 1;
            As[buf][ak + 0][ar] = av.x;
            As[buf][ak + 1][ar] = av.y;
            As[buf][ak + 2][ar] = av.z;
            As[buf][ak + 3][ar] = av.w;
            *(float4*)&Bs[buf][bk][bn] = bv;
            __syncthreads();
        }
    }

    // epilogue (float4 stores)
#pragma unroll
    for (int ih = 0; ih < 2; ih++) {
#pragma unroll
        for (int i = 0; i < 4; i++) {
            const int m = row0 + ih * 64 + ty * 4 + i;
            const size_t rowoff = (size_t)m * ldC;
#pragma unroll
            for (int jh = 0; jh < 2; jh++) {
                const int nn = n0 + jh * 64 + tx * 4;
                const float4 b4 = *(const float4*)&bb[nn];
                float4 v;
                v.x = c[ih * 4 + i][jh * 4 + 0] + b4.x;
                v.y = c[ih * 4 + i][jh * 4 + 1] + b4.y;
                v.z = c[ih * 4 + i][jh * 4 + 2] + b4.z;
                v.w = c[ih * 4 + i][jh * 4 + 3] + b4.w;
                if (epi == 1) {
                    v.x = fmaxf(v.x, 0.f); v.y = fmaxf(v.y, 0.f);
                    v.z = fmaxf(v.z, 0.f); v.w = fmaxf(v.w, 0.f);
                }
                if (epi >= 2) {
                    const float4 r = *(const float4*)&R1b[rowoff + nn];
                    v.x += r.x; v.y += r.y; v.z += r.z; v.w += r.w;
                }
                if (epi == 3) {
                    const float4 r = *(const float4*)&R2b[rowoff + nn];
                    v.x += r.x; v.y += r.y; v.z += r.z; v.w += r.w;
                }
                *(float4*)&Cb[rowoff + nn] = v;
            }
        }
    }
}

// ---------------------------------------------------------------------------
// Temporal attention: one block per (b, n, h). Causal, with relative-position
// key/value embeddings. q row held in registers; K/V + rel tables in smem.
// ---------------------------------------------------------------------------
__global__ void __launch_bounds__(128) temporal_attn(
    const float* __restrict__ q, const float* __restrict__ k,
    const float* __restrict__ v,
    const float* __restrict__ relk, const float* __restrict__ relv,
    float* __restrict__ out)
{
    __shared__ float ks[Tt][DPp];
    __shared__ float vs[Tt][DPp];
    __shared__ float rk[33][DPp];
    __shared__ float rv[33][DPp];

    const int bid = blockIdx.x;
    const int b = bid / (Nj * Hh);
    const int rem = bid % (Nj * Hh);
    const int n = rem / Hh;
    const int h = rem % Hh;
    const int tid = threadIdx.x;

    const size_t base = ((size_t)b * Tt * Nj + n) * Dd + h * DPp;  // t stride = LDJ

    {
        const float4* k4 = reinterpret_cast<const float4*>(k);
        const float4* v4 = reinterpret_cast<const float4*>(v);
        for (int idx = tid; idx < Tt * 8; idx += 128) {
            const int t = idx >> 3, c = idx & 7;
            const size_t g = (base + (size_t)t * LDJ) / 4 + c;
            reinterpret_cast<float4*>(&ks[t][0])[c] = k4[g];
            reinterpret_cast<float4*>(&vs[t][0])[c] = v4[g];
        }
        const float4* rk4 = reinterpret_cast<const float4*>(relk);
        const float4* rv4 = reinterpret_cast<const float4*>(relv);
        for (int idx = tid; idx < 33 * 8; idx += 128) {
            reinterpret_cast<float4*>(&rk[0][0])[idx] = rk4[idx];
            reinterpret_cast<float4*>(&rv[0][0])[idx] = rv4[idx];
        }
    }
    __syncthreads();

    const int t = tid;
    if (t < Tt) {
        float qreg[DPp];
        {
            const float4* q4 = reinterpret_cast<const float4*>(q + base + (size_t)t * LDJ);
#pragma unroll
            for (int i = 0; i < 8; i++) {
                float4 vq = q4[i];
                qreg[4 * i + 0] = vq.x; qreg[4 * i + 1] = vq.y;
                qreg[4 * i + 2] = vq.z; qreg[4 * i + 3] = vq.w;
            }
        }
        float pr[33];
        for (int jj = 0; jj < 33; jj++) {
            float s = 0.f;
#pragma unroll
            for (int d = 0; d < DPp; d++) s += qreg[d] * rk[jj][d];
            pr[jj] = s;
        }

        const float scale = 0.17677669529663687f;  // 1/sqrt(32)
        float prob[Tt];
        float mx = -1e30f;
        for (int s = 0; s < Tt; s++) {
            float dot = 0.f;
#pragma unroll
            for (int d = 0; d < DPp; d++) dot += qreg[d] * ks[s][d];
            int jj = s - t + 32;
            if (jj < 0) jj = 0;
            if (jj > 32) jj = 32;
            const float lg = (s <= t) ? (dot + pr[jj]) * scale : -1e30f;
            prob[s] = lg;
            mx = fmaxf(mx, lg);
        }
        float sum = 0.f;
        for (int s = 0; s < Tt; s++) {
            const float e = __expf(prob[s] - mx);
            prob[s] = e;
            sum += e;
        }
        const float inv = 1.f / sum;
        float wsum[33];
        for (int jj = 0; jj < 33; jj++) wsum[jj] = 0.f;
        for (int s = 0; s < Tt; s++) {
            prob[s] *= inv;
            int jj = s - t + 32;
            if (jj < 0) jj = 0;
            if (jj > 32) jj = 32;
            wsum[jj] += prob[s];
        }
        for (int d = 0; d < DPp; d++) {
            float acc = 0.f;
            for (int s = 0; s < Tt; s++) acc += prob[s] * vs[s][d];
            for (int jj = 0; jj < 33; jj++) acc += wsum[jj] * rv[jj][d];
            out[base + (size_t)t * LDJ + d] = acc;
        }
    }
}

// ---------------------------------------------------------------------------
// Spatial attention: one block (1 warp) per (b*t, h). 24 joints, no mask.
// ---------------------------------------------------------------------------
__global__ void __launch_bounds__(32) spatial_attn(
    const float* __restrict__ q, const float* __restrict__ k,
    const float* __restrict__ v, float* __restrict__ out)
{
    __shared__ float ks[Nj][DPp];
    __shared__ float vs[Nj][DPp];

    const int bid = blockIdx.x;       // B*T*H
    const int bt = bid / Hh;
    const int h = bid % Hh;
    const size_t base = (size_t)bt * LDJ + h * DPp;
    const int tid = threadIdx.x;

    {
        const float4* k4 = reinterpret_cast<const float4*>(k);
        const float4* v4 = reinterpret_cast<const float4*>(v);
        for (int idx = tid; idx < Nj * 8; idx += 32) {
            const int nn = idx >> 3, c = idx & 7;
            const size_t g = (base + (size_t)nn * Dd) / 4 + c;
            reinterpret_cast<float4*>(&ks[nn][0])[c] = k4[g];
            reinterpret_cast<float4*>(&vs[nn][0])[c] = v4[g];
        }
    }
    __syncwarp();

    const int nn = tid;
    if (nn < Nj) {
        float qreg[DPp];
        {
            const float4* q4 = reinterpret_cast<const float4*>(q + base + (size_t)nn * Dd);
#pragma unroll
            for (int i = 0; i < 8; i++) {
                float4 vq = q4[i];
                qreg[4 * i + 0] = vq.x; qreg[4 * i + 1] = vq.y;
                qreg[4 * i + 2] = vq.z; qreg[4 * i + 3] = vq.w;
            }
        }
        const float scale = 0.17677669529663687f;
        float prob[Nj];
        float mx = -1e30f;
        for (int m = 0; m < Nj; m++) {
            float dot = 0.f;
#pragma unroll
            for (int d = 0; d < DPp; d++) dot += qreg[d] * ks[m][d];
            dot *= scale;
            prob[m] = dot;
            mx = fmaxf(mx, dot);
        }
        float sum = 0.f;
        for (int m = 0; m < Nj; m++) {
            const float e = __expf(prob[m] - mx);
            prob[m] = e;
            sum += e;
        }
        const float inv = 1.f / sum;
        for (int m = 0; m < Nj; m++) prob[m] *= inv;
        for (int d = 0; d < DPp; d++) {
            float acc = 0.f;
            for (int m = 0; m < Nj; m++) acc += prob[m] * vs[m][d];
            out[base + (size_t)nn * Dd + d] = acc;
        }
    }
}

// ---------------------------------------------------------------------------
extern "C" void kernel_launch(void* const* d_in, const int* in_sizes, int n_in,
                              void* d_out, int out_size)
{
    const float* x     = (const float*)d_in[0];
    // d_in[1] = mask (causal handled analytically)
    const float* wq_t  = (const float*)d_in[2];
    const float* wk_t  = (const float*)d_in[3];
    const float* wv_t  = (const float*)d_in[4];
    const float* bq_t  = (const float*)d_in[5];
    const float* bk_t  = (const float*)d_in[6];
    const float* bv_t  = (const float*)d_in[7];
    const float* wo_t  = (const float*)d_in[8];
    const float* bo_t  = (const float*)d_in[9];
    const float* relk  = (const float*)d_in[10];
    const float* relv  = (const float*)d_in[11];
    const float* wq_s  = (const float*)d_in[12];
    const float* wk_s  = (const float*)d_in[13];
    const float* wv_s  = (const float*)d_in[14];
    const float* wo_s  = (const float*)d_in[15];
    const float* bq_s  = (const float*)d_in[16];
    const float* bk_s  = (const float*)d_in[17];
    const float* bv_s  = (const float*)d_in[18];
    const float* bo_s  = (const float*)d_in[19];
    const float* ff1w  = (const float*)d_in[20];
    const float* ff1b  = (const float*)d_in[21];
    const float* ff2w  = (const float*)d_in[22];
    const float* ff2b  = (const float*)d_in[23];
    float* out = (float*)d_out;

    float *qt, *kt, *vt, *qs, *ks_, *vs, *ta, *sa, *to, *y, *hh;
    cudaGetSymbolAddress((void**)&qt,  g_qt);
    cudaGetSymbolAddress((void**)&kt,  g_kt);
    cudaGetSymbolAddress((void**)&vt,  g_vt);
    cudaGetSymbolAddress((void**)&qs,  g_qs);
    cudaGetSymbolAddress((void**)&ks_, g_ks);
    cudaGetSymbolAddress((void**)&vs,  g_vs);
    cudaGetSymbolAddress((void**)&ta,  g_ta);
    cudaGetSymbolAddress((void**)&sa,  g_sa);
    cudaGetSymbolAddress((void**)&to,  g_to);
    cudaGetSymbolAddress((void**)&y,   g_y);
    cudaGetSymbolAddress((void**)&hh,  g_h);

    const dim3 gJ(15, 2, 24);    // per-joint GEMMs: M=1920 per joint, 128x128 tiles
    const dim3 gC(360, 2, 1);    // contiguous GEMMs: M=46080

    // temporal QKV (per-joint weights)
    gemm256<<<gJ, 256>>>(x, LDJ, Dd, wq_t, Dd * Dd, bq_t, Dd, qt, LDJ, Dd, nullptr, nullptr, 0);
    gemm256<<<gJ, 256>>>(x, LDJ, Dd, wk_t, Dd * Dd, bk_t, Dd, kt, LDJ, Dd, nullptr, nullptr, 0);
    gemm256<<<gJ, 256>>>(x, LDJ, Dd, wv_t, Dd * Dd, bv_t, Dd, vt, LDJ, Dd, nullptr, nullptr, 0);
    // spatial QKV (shared weights)
    gemm256<<<gC, 256>>>(x, Dd, 0, wq_s, 0, bq_s, 0, qs, Dd, 0, nullptr, nullptr, 0);
    gemm256<<<gC, 256>>>(x, Dd, 0, wk_s, 0, bk_s, 0, ks_, Dd, 0, nullptr, nullptr, 0);
    gemm256<<<gC, 256>>>(x, Dd, 0, wv_s, 0, bv_s, 0, vs, Dd, 0, nullptr, nullptr, 0);

    temporal_attn<<<Bq * Nj * Hh, 128>>>(qt, kt, vt, relk, relv, ta);
    spatial_attn<<<Bq * Tt * Hh, 32>>>(qs, ks_, vs, sa);

    // output projections; wo_s epilogue fuses y = x + t_out + s_out
    gemm256<<<gC, 256>>>(ta, Dd, 0, wo_t, 0, bo_t, 0, to, Dd, 0, nullptr, nullptr, 0);
    gemm256<<<gC, 256>>>(sa, Dd, 0, wo_s, 0, bo_s, 0, y, Dd, 0, x, to, 3);

    // per-joint FFN; ff2 epilogue fuses the residual and writes final output
    gemm256<<<gJ, 256>>>(y, LDJ, Dd, ff1w, Dd * Dd, ff1b, Dd, hh, LDJ, Dd, nullptr, nullptr, 1);
    gemm256<<<gJ, 256>>>(hh, LDJ, Dd, ff2w, Dd * Dd, ff2b, Dd, out, LDJ, Dd, y, nullptr, 2);
}

// round 16
// speedup vs baseline: 2.2880x; 2.2880x over previous
#include <cuda_runtime.h>
#include <cuda_bf16.h>
#include <cstdint>
#include <math.h>

// dims
#define Bq 16
#define Tt 120
#define Nj 24
#define Dd 256
#define Hh 8
#define DPp 32
#define TOT (Bq*Tt*Nj*Dd)   // 11,796,480
#define LDJ (Nj*Dd)         // 6144

// scratch buffers (static device memory is allowed; cudaMalloc is not)
__device__ float g_qt[TOT];
__device__ float g_kt[TOT];
__device__ float g_vt[TOT];
__device__ float g_qs[TOT];
__device__ float g_ks[TOT];
__device__ float g_vs[TOT];
__device__ float g_ta[TOT];
__device__ float g_sa[TOT];
__device__ float g_to[TOT];
__device__ float g_y[TOT];
__device__ float g_h[TOT];

// transposed + split weights: 125 matrices of 256x256, [N][K] bf16 layout
// slots: wq_t:0..23, wk_t:24..47, wv_t:48..71, wo_t:72, wq_s:73, wk_s:74,
//        wv_s:75, wo_s:76, ff1:77..100, ff2:101..124
#define NMATS 125
__device__ __align__(16) __nv_bfloat16 g_whi[NMATS * 65536];
__device__ __align__(16) __nv_bfloat16 g_wlo[NMATS * 65536];

// ============================ helpers ==================================
__device__ __forceinline__ uint32_t smem_to_u32(const void* p) {
    uint32_t a;
    asm("{ .reg .u64 t; cvta.to.shared.u64 t, %1; cvt.u32.u64 %0, t; }"
        : "=r"(a) : "l"(p));
    return a;
}
#define SMEM_SWIZZLE_128B(o) ((o) ^ (((o) >> 3) & 0x70))

__device__ __forceinline__ uint32_t pack_bf16(float x, float y) {
    __nv_bfloat162 t = __floats2bfloat162_rn(x, y);
    return *(uint32_t*)&t;
}

// ldmatrix x4: portable (sm_75+)
#define LDSM4(r, addr) \
    asm volatile("ldmatrix.sync.aligned.m8n8.x4.shared.b16 {%0,%1,%2,%3}, [%4];" \
        : "=r"((r)[0]), "=r"((r)[1]), "=r"((r)[2]), "=r"((r)[3]) : "r"(addr))

// bf16 mma m16n8k16, fp32 accum: portable (sm_80+)
#define MMA_BF16(d, a, b) \
    asm volatile("mma.sync.aligned.m16n8k16.row.col.f32.bf16.bf16.f32 " \
        "{%0,%1,%2,%3}, {%4,%5,%6,%7}, {%8,%9}, {%0,%1,%2,%3};" \
        : "+f"((d)[0]), "+f"((d)[1]), "+f"((d)[2]), "+f"((d)[3]) \
        : "r"((a)[0]), "r"((a)[1]), "r"((a)[2]), "r"((a)[3]), \
          "r"((b)[0]), "r"((b)[1]))

// ================== weight prep: transpose [K,N]->[N,K] + bf16 split ========
__global__ void __launch_bounds__(256) prep_w(
    const float* __restrict__ W, __nv_bfloat16* __restrict__ Whi,
    __nv_bfloat16* __restrict__ Wlo)
{
    __shared__ float sm[32][33];
    const int j = blockIdx.y;
    const int ti = blockIdx.x >> 3, tj = blockIdx.x & 7;
    const int k0 = ti * 32, n0 = tj * 32;
    const float* Wb = W + (size_t)j * 65536;
    const int c = threadIdx.x & 31, r0 = threadIdx.x >> 5;
#pragma unroll
    for (int p = 0; p < 4; p++) {
        const int r = r0 + p * 8;
        sm[r][c] = Wb[(size_t)(k0 + r) * 256 + n0 + c];
    }
    __syncthreads();
    __nv_bfloat16* Hb = Whi + (size_t)j * 65536;
    __nv_bfloat16* Lb = Wlo + (size_t)j * 65536;
#pragma unroll
    for (int p = 0; p < 4; p++) {
        const int rr = r0 + p * 8;
        const float a = sm[c][rr];
        const __nv_bfloat16 h = __float2bfloat16(a);
        const __nv_bfloat16 l = __float2bfloat16(a - __bfloat162float(h));
        const size_t o = (size_t)(n0 + rr) * 256 + k0 + c;
        Hb[o] = h;
        Lb[o] = l;
    }
}

// ====================== mma.sync split-bf16 GEMM ============================
// C[M,256] = A[M,256] @ W^T + bias, W stored [N][K] bf16 (hi/lo split).
// CTA: 128(M) x 128(N), 8 warps as 4(m) x 2(n), warp tile 32x64.
// K in 4 chunks of 64. SW128-xor swizzled smem, ldmatrix fragments.
// epi: 0=bias, 1=bias+relu, 2=bias+R1, 3=bias+R1+R2
#define OFF_AHI 0
#define OFF_ALO 16384
#define OFF_BHI 32768
#define OFF_BLO 49152
#define SM_GTOT 65536

__global__ void __launch_bounds__(256, 2) gemm_mma(
    const float* __restrict__ A, int ldA, int aJ,
    const __nv_bfloat16* __restrict__ Whi, const __nv_bfloat16* __restrict__ Wlo,
    const float* __restrict__ bias, int bJ,
    float* __restrict__ C, int ldC, int cJ,
    const float* __restrict__ R1, const float* __restrict__ R2, int epi)
{
    extern __shared__ char smem[];
    const uint32_t sb = smem_to_u32(smem);
    const int tid = threadIdx.x;
    const int wid = tid >> 5;
    const int lane = tid & 31;
    const int wm = wid >> 1;          // 0..3 -> m offset wm*32
    const int wn = wid & 1;           // 0..1 -> n offset wn*64

    const int j = blockIdx.z;
    const size_t rowbase = (size_t)blockIdx.x * 128;
    const int n0 = blockIdx.y * 128;

    const float* Ab = A + (size_t)j * aJ + rowbase * ldA;
    const char* WhiB = (const char*)(Whi + (size_t)j * 65536 + (size_t)n0 * 256);
    const char* WloB = (const char*)(Wlo + (size_t)j * 65536 + (size_t)n0 * 256);

    float acc[2][8][4];
#pragma unroll
    for (int mf = 0; mf < 2; mf++)
#pragma unroll
        for (int nf = 0; nf < 8; nf++)
#pragma unroll
            for (int q = 0; q < 4; q++) acc[mf][nf][q] = 0.f;

    // precomputed ldmatrix lane addressing
    const int g = lane >> 3, li = lane & 7;

    for (int c = 0; c < 4; c++) {
        __syncthreads();
        // ---- A chunk: 128 rows x 64 fp32 -> bf16 hi/lo, swizzled ----------
#pragma unroll
        for (int p = 0; p < 8; p++) {
            const int idx = p * 256 + tid;
            const int r = idx >> 4, f4 = idx & 15;
            const float4 av = *(const float4*)(Ab + (size_t)r * ldA + c * 64 + f4 * 4);
            const __nv_bfloat16 h0 = __float2bfloat16(av.x);
            const __nv_bfloat16 h1 = __float2bfloat16(av.y);
            const __nv_bfloat16 h2 = __float2bfloat16(av.z);
            const __nv_bfloat16 h3 = __float2bfloat16(av.w);
            uint2 hv, lv;
            hv.x = pack_bf16(av.x, av.y);
            hv.y = pack_bf16(av.z, av.w);
            lv.x = pack_bf16(av.x - __bfloat162float(h0), av.y - __bfloat162float(h1));
            lv.y = pack_bf16(av.z - __bfloat162float(h2), av.w - __bfloat162float(h3));
            const uint32_t sw = SMEM_SWIZZLE_128B((uint32_t)(r * 128 + f4 * 8));
            *(uint2*)(smem + OFF_AHI + sw) = hv;
            *(uint2*)(smem + OFF_ALO + sw) = lv;
        }
        // ---- B chunk: 128 n-rows x 64 k (pre-split bf16), swizzled --------
#pragma unroll
        for (int p = 0; p < 4; p++) {
            const int idx = p * 256 + tid;
            const int n = idx >> 3, seg = idx & 7;
            const size_t go = (size_t)n * 512 + c * 128 + seg * 16;
            const uint32_t sw = SMEM_SWIZZLE_128B((uint32_t)(n * 128 + seg * 16));
            *(uint4*)(smem + OFF_BHI + sw) = *(const uint4*)(WhiB + go);
            *(uint4*)(smem + OFF_BLO + sw) = *(const uint4*)(WloB + go);
        }
        __syncthreads();

#pragma unroll
        for (int ks = 0; ks < 4; ks++) {
            // A fragments for both m16 halves (hi and lo)
            uint32_t a_hi[2][4], a_lo[2][4];
#pragma unroll
            for (int mf = 0; mf < 2; mf++) {
                const int arow = wm * 32 + mf * 16 + (g & 1) * 8 + li;
                const uint32_t bo = (uint32_t)(arow * 128 + ks * 32 + (g >> 1) * 16);
                const uint32_t sw = SMEM_SWIZZLE_128B(bo);
                LDSM4(a_hi[mf], sb + OFF_AHI + sw);
                LDSM4(a_lo[mf], sb + OFF_ALO + sw);
            }
            // B fragments: 4 x (two n8k16 frags per ldmatrix.x4)
#pragma unroll
            for (int p2 = 0; p2 < 4; p2++) {
                const int nrow = wn * 64 + p2 * 16 + (g >> 1) * 8 + li;
                const uint32_t bo = (uint32_t)(nrow * 128 + ks * 32 + (g & 1) * 16);
                const uint32_t sw = SMEM_SWIZZLE_128B(bo);
                uint32_t bh[4], bl[4];
                LDSM4(bh, sb + OFF_BHI + sw);
                LDSM4(bl, sb + OFF_BLO + sw);
#pragma unroll
                for (int mf = 0; mf < 2; mf++) {
#pragma unroll
                    for (int h2 = 0; h2 < 2; h2++) {
                        const int nf = p2 * 2 + h2;
                        MMA_BF16(acc[mf][nf], a_hi[mf], bh + h2 * 2);
                        MMA_BF16(acc[mf][nf], a_hi[mf], bl + h2 * 2);
                        MMA_BF16(acc[mf][nf], a_lo[mf], bh + h2 * 2);
                    }
                }
            }
        }
    }

    // ---- epilogue: registers -> gmem, fused bias/relu/residuals -----------
    const float* bb = bias + (size_t)j * bJ;
    float* Cb = C + (size_t)j * cJ + rowbase * ldC;
    const float* R1b = R1 ? (R1 + (size_t)j * cJ + rowbase * ldC) : nullptr;
    const float* R2b = R2 ? (R2 + (size_t)j * cJ + rowbase * ldC) : nullptr;

#pragma unroll
    for (int mf = 0; mf < 2; mf++) {
        const int r0 = wm * 32 + mf * 16 + (lane >> 2);
        const int r1 = r0 + 8;
#pragma unroll
        for (int nf = 0; nf < 8; nf++) {
            const int cc = n0 + wn * 64 + nf * 8 + (lane & 3) * 2;
            const float2 b2 = *(const float2*)&bb[cc];
            float2 v0, v1;
            v0.x = acc[mf][nf][0] + b2.x;
            v0.y = acc[mf][nf][1] + b2.y;
            v1.x = acc[mf][nf][2] + b2.x;
            v1.y = acc[mf][nf][3] + b2.y;
            if (epi == 1) {
                v0.x = fmaxf(v0.x, 0.f); v0.y = fmaxf(v0.y, 0.f);
                v1.x = fmaxf(v1.x, 0.f); v1.y = fmaxf(v1.y, 0.f);
            }
            const size_t o0 = (size_t)r0 * ldC + cc;
            const size_t o1 = (size_t)r1 * ldC + cc;
            if (epi >= 2) {
                const float2 a0 = *(const float2*)&R1b[o0];
                const float2 a1 = *(const float2*)&R1b[o1];
                v0.x += a0.x; v0.y += a0.y; v1.x += a1.x; v1.y += a1.y;
            }
            if (epi == 3) {
                const float2 a0 = *(const float2*)&R2b[o0];
                const float2 a1 = *(const float2*)&R2b[o1];
                v0.x += a0.x; v0.y += a0.y; v1.x += a1.x; v1.y += a1.y;
            }
            *(float2*)&Cb[o0] = v0;
            *(float2*)&Cb[o1] = v1;
        }
    }
}

// ---------------------------------------------------------------------------
// Temporal attention: one block per (b, n, h). Causal, with relative-position
// key/value embeddings. (unchanged, known-good)
// ---------------------------------------------------------------------------
__global__ void __launch_bounds__(128) temporal_attn(
    const float* __restrict__ q, const float* __restrict__ k,
    const float* __restrict__ v,
    const float* __restrict__ relk, const float* __restrict__ relv,
    float* __restrict__ out)
{
    __shared__ float ks[Tt][DPp];
    __shared__ float vs[Tt][DPp];
    __shared__ float rk[33][DPp];
    __shared__ float rv[33][DPp];

    const int bid = blockIdx.x;
    const int b = bid / (Nj * Hh);
    const int rem = bid % (Nj * Hh);
    const int n = rem / Hh;
    const int h = rem % Hh;
    const int tid = threadIdx.x;

    const size_t base = ((size_t)b * Tt * Nj + n) * Dd + h * DPp;

    {
        const float4* k4 = reinterpret_cast<const float4*>(k);
        const float4* v4 = reinterpret_cast<const float4*>(v);
        for (int idx = tid; idx < Tt * 8; idx += 128) {
            const int t = idx >> 3, c = idx & 7;
            const size_t g = (base + (size_t)t * LDJ) / 4 + c;
            reinterpret_cast<float4*>(&ks[t][0])[c] = k4[g];
            reinterpret_cast<float4*>(&vs[t][0])[c] = v4[g];
        }
        const float4* rk4 = reinterpret_cast<const float4*>(relk);
        const float4* rv4 = reinterpret_cast<const float4*>(relv);
        for (int idx = tid; idx < 33 * 8; idx += 128) {
            reinterpret_cast<float4*>(&rk[0][0])[idx] = rk4[idx];
            reinterpret_cast<float4*>(&rv[0][0])[idx] = rv4[idx];
        }
    }
    __syncthreads();

    const int t = tid;
    if (t < Tt) {
        float qreg[DPp];
        {
            const float4* q4 = reinterpret_cast<const float4*>(q + base + (size_t)t * LDJ);
#pragma unroll
            for (int i = 0; i < 8; i++) {
                float4 vq = q4[i];
                qreg[4 * i + 0] = vq.x; qreg[4 * i + 1] = vq.y;
                qreg[4 * i + 2] = vq.z; qreg[4 * i + 3] = vq.w;
            }
        }
        float pr[33];
        for (int jj = 0; jj < 33; jj++) {
            float s = 0.f;
#pragma unroll
            for (int d = 0; d < DPp; d++) s += qreg[d] * rk[jj][d];
            pr[jj] = s;
        }

        const float scale = 0.17677669529663687f;
        float prob[Tt];
        float mx = -1e30f;
        for (int s = 0; s < Tt; s++) {
            float dot = 0.f;
#pragma unroll
            for (int d = 0; d < DPp; d++) dot += qreg[d] * ks[s][d];
            int jj = s - t + 32;
            if (jj < 0) jj = 0;
            if (jj > 32) jj = 32;
            const float lg = (s <= t) ? (dot + pr[jj]) * scale : -1e30f;
            prob[s] = lg;
            mx = fmaxf(mx, lg);
        }
        float sum = 0.f;
        for (int s = 0; s < Tt; s++) {
            const float e = __expf(prob[s] - mx);
            prob[s] = e;
            sum += e;
        }
        const float inv = 1.f / sum;
        float wsum[33];
        for (int jj = 0; jj < 33; jj++) wsum[jj] = 0.f;
        for (int s = 0; s < Tt; s++) {
            prob[s] *= inv;
            int jj = s - t + 32;
            if (jj < 0) jj = 0;
            if (jj > 32) jj = 32;
            wsum[jj] += prob[s];
        }
        for (int d = 0; d < DPp; d++) {
            float acc = 0.f;
            for (int s = 0; s < Tt; s++) acc += prob[s] * vs[s][d];
            for (int jj = 0; jj < 33; jj++) acc += wsum[jj] * rv[jj][d];
            out[base + (size_t)t * LDJ + d] = acc;
        }
    }
}

// ---------------------------------------------------------------------------
// Spatial attention: one block (1 warp) per (b*t, h). (unchanged)
// ---------------------------------------------------------------------------
__global__ void __launch_bounds__(32) spatial_attn(
    const float* __restrict__ q, const float* __restrict__ k,
    const float* __restrict__ v, float* __restrict__ out)
{
    __shared__ float ks[Nj][DPp];
    __shared__ float vs[Nj][DPp];

    const int bid = blockIdx.x;
    const int bt = bid / Hh;
    const int h = bid % Hh;
    const size_t base = (size_t)bt * LDJ + h * DPp;
    const int tid = threadIdx.x;

    {
        const float4* k4 = reinterpret_cast<const float4*>(k);
        const float4* v4 = reinterpret_cast<const float4*>(v);
        for (int idx = tid; idx < Nj * 8; idx += 32) {
            const int nn = idx >> 3, c = idx & 7;
            const size_t g = (base + (size_t)nn * Dd) / 4 + c;
            reinterpret_cast<float4*>(&ks[nn][0])[c] = k4[g];
            reinterpret_cast<float4*>(&vs[nn][0])[c] = v4[g];
        }
    }
    __syncwarp();

    const int nn = tid;
    if (nn < Nj) {
        float qreg[DPp];
        {
            const float4* q4 = reinterpret_cast<const float4*>(q + base + (size_t)nn * Dd);
#pragma unroll
            for (int i = 0; i < 8; i++) {
                float4 vq = q4[i];
                qreg[4 * i + 0] = vq.x; qreg[4 * i + 1] = vq.y;
                qreg[4 * i + 2] = vq.z; qreg[4 * i + 3] = vq.w;
            }
        }
        const float scale = 0.17677669529663687f;
        float prob[Nj];
        float mx = -1e30f;
        for (int m = 0; m < Nj; m++) {
            float dot = 0.f;
#pragma unroll
            for (int d = 0; d < DPp; d++) dot += qreg[d] * ks[m][d];
            dot *= scale;
            prob[m] = dot;
            mx = fmaxf(mx, dot);
        }
        float sum = 0.f;
        for (int m = 0; m < Nj; m++) {
            const float e = __expf(prob[m] - mx);
            prob[m] = e;
            sum += e;
        }
        const float inv = 1.f / sum;
        for (int m = 0; m < Nj; m++) prob[m] *= inv;
        for (int d = 0; d < DPp; d++) {
            float acc = 0.f;
            for (int m = 0; m < Nj; m++) acc += prob[m] * vs[m][d];
            out[base + (size_t)nn * Dd + d] = acc;
        }
    }
}

// ---------------------------------------------------------------------------
extern "C" void kernel_launch(void* const* d_in, const int* in_sizes, int n_in,
                              void* d_out, int out_size)
{
    const float* x     = (const float*)d_in[0];
    const float* wq_t  = (const float*)d_in[2];
    const float* wk_t  = (const float*)d_in[3];
    const float* wv_t  = (const float*)d_in[4];
    const float* bq_t  = (const float*)d_in[5];
    const float* bk_t  = (const float*)d_in[6];
    const float* bv_t  = (const float*)d_in[7];
    const float* wo_t  = (const float*)d_in[8];
    const float* bo_t  = (const float*)d_in[9];
    const float* relk  = (const float*)d_in[10];
    const float* relv  = (const float*)d_in[11];
    const float* wq_s  = (const float*)d_in[12];
    const float* wk_s  = (const float*)d_in[13];
    const float* wv_s  = (const float*)d_in[14];
    const float* wo_s  = (const float*)d_in[15];
    const float* bq_s  = (const float*)d_in[16];
    const float* bk_s  = (const float*)d_in[17];
    const float* bv_s  = (const float*)d_in[18];
    const float* bo_s  = (const float*)d_in[19];
    const float* ff1w  = (const float*)d_in[20];
    const float* ff1b  = (const float*)d_in[21];
    const float* ff2w  = (const float*)d_in[22];
    const float* ff2b  = (const float*)d_in[23];
    float* out = (float*)d_out;

    float *qt, *kt, *vt, *qs, *ks_, *vs, *ta, *sa, *to, *y, *hh;
    __nv_bfloat16 *whi, *wlo;
    cudaGetSymbolAddress((void**)&qt,  g_qt);
    cudaGetSymbolAddress((void**)&kt,  g_kt);
    cudaGetSymbolAddress((void**)&vt,  g_vt);
    cudaGetSymbolAddress((void**)&qs,  g_qs);
    cudaGetSymbolAddress((void**)&ks_, g_ks);
    cudaGetSymbolAddress((void**)&vs,  g_vs);
    cudaGetSymbolAddress((void**)&ta,  g_ta);
    cudaGetSymbolAddress((void**)&sa,  g_sa);
    cudaGetSymbolAddress((void**)&to,  g_to);
    cudaGetSymbolAddress((void**)&y,   g_y);
    cudaGetSymbolAddress((void**)&hh,  g_h);
    cudaGetSymbolAddress((void**)&whi, g_whi);
    cudaGetSymbolAddress((void**)&wlo, g_wlo);

    cudaFuncSetAttribute(gemm_mma, cudaFuncAttributeMaxDynamicSharedMemorySize, SM_GTOT);

    // ---- weight prep: transpose + bf16 split ----
    const size_t MSZ = 65536;
    prep_w<<<dim3(64, 24), 256>>>(wq_t, whi +   0 * MSZ, wlo +   0 * MSZ);
    prep_w<<<dim3(64, 24), 256>>>(wk_t, whi +  24 * MSZ, wlo +  24 * MSZ);
    prep_w<<<dim3(64, 24), 256>>>(wv_t, whi +  48 * MSZ, wlo +  48 * MSZ);
    prep_w<<<dim3(64,  1), 256>>>(wo_t, whi +  72 * MSZ, wlo +  72 * MSZ);
    prep_w<<<dim3(64,  1), 256>>>(wq_s, whi +  73 * MSZ, wlo +  73 * MSZ);
    prep_w<<<dim3(64,  1), 256>>>(wk_s, whi +  74 * MSZ, wlo +  74 * MSZ);
    prep_w<<<dim3(64,  1), 256>>>(wv_s, whi +  75 * MSZ, wlo +  75 * MSZ);
    prep_w<<<dim3(64,  1), 256>>>(wo_s, whi +  76 * MSZ, wlo +  76 * MSZ);
    prep_w<<<dim3(64, 24), 256>>>(ff1w, whi +  77 * MSZ, wlo +  77 * MSZ);
    prep_w<<<dim3(64, 24), 256>>>(ff2w, whi + 101 * MSZ, wlo + 101 * MSZ);

    const dim3 gJ(15, 2, 24);    // per-joint: M=1920 per joint, 128x128 tiles
    const dim3 gC(360, 2, 1);    // contiguous: M=46080

    // temporal QKV (per-joint weights)
    gemm_mma<<<gJ, 256, SM_GTOT>>>(x, LDJ, Dd, whi + 0 * MSZ,  wlo + 0 * MSZ,  bq_t, Dd, qt, LDJ, Dd, nullptr, nullptr, 0);
    gemm_mma<<<gJ, 256, SM_GTOT>>>(x, LDJ, Dd, whi + 24 * MSZ, wlo + 24 * MSZ, bk_t, Dd, kt, LDJ, Dd, nullptr, nullptr, 0);
    gemm_mma<<<gJ, 256, SM_GTOT>>>(x, LDJ, Dd, whi + 48 * MSZ, wlo + 48 * MSZ, bv_t, Dd, vt, LDJ, Dd, nullptr, nullptr, 0);
    // spatial QKV (shared weights)
    gemm_mma<<<gC, 256, SM_GTOT>>>(x, Dd, 0, whi + 73 * MSZ, wlo + 73 * MSZ, bq_s, 0, qs, Dd, 0, nullptr, nullptr, 0);
    gemm_mma<<<gC, 256, SM_GTOT>>>(x, Dd, 0, whi + 74 * MSZ, wlo + 74 * MSZ, bk_s, 0, ks_, Dd, 0, nullptr, nullptr, 0);
    gemm_mma<<<gC, 256, SM_GTOT>>>(x, Dd, 0, whi + 75 * MSZ, wlo + 75 * MSZ, bv_s, 0, vs, Dd, 0, nullptr, nullptr, 0);

    temporal_attn<<<Bq * Nj * Hh, 128>>>(qt, kt, vt, relk, relv, ta);
    spatial_attn<<<Bq * Tt * Hh, 32>>>(qs, ks_, vs, sa);

    // output projections; wo_s epilogue fuses y = x + t_out + s_out
    gemm_mma<<<gC, 256, SM_GTOT>>>(ta, Dd, 0, whi + 72 * MSZ, wlo + 72 * MSZ, bo_t, 0, to, Dd, 0, nullptr, nullptr, 0);
    gemm_mma<<<gC, 256, SM_GTOT>>>(sa, Dd, 0, whi + 76 * MSZ, wlo + 76 * MSZ, bo_s, 0, y, Dd, 0, x, to, 3);

    // per-joint FFN; ff2 epilogue fuses residual, writes final output
    gemm_mma<<<gJ, 256, SM_GTOT>>>(y, LDJ, Dd, whi + 77 * MSZ,  wlo + 77 * MSZ,  ff1b, Dd, hh, LDJ, Dd, nullptr, nullptr, 1);
    gemm_mma<<<gJ, 256, SM_GTOT>>>(hh, LDJ, Dd, whi + 101 * MSZ, wlo + 101 * MSZ, ff2b, Dd, out, LDJ, Dd, y, nullptr, 2);
}